// round 1
// baseline (speedup 1.0000x reference)
#include <cuda_runtime.h>
#include <math.h>

#define BB 16
#define NN 8192
#define CC 128
#define KK 128
#define LL 4
#define J1 257          // 2K + 1 (cos rows, sin rows, mask row)
#define JA 392          // 385 (2K + 1 + C) padded to multiple of 8
#define NSPLIT 8

// ---------------- scratch (device globals; no allocation allowed) ----------
__device__ float g_bases[(size_t)BB * J1 * NN];          // [b][j][x]; j<128 cos, <256 sin, 256 mask
__device__ float g_wsz[BB * NN];                         // weights * size
__device__ float g_h[2][(size_t)BB * CC * NN];           // ping-pong h
__device__ float g_part[(size_t)NSPLIT * BB * CC * J1];  // split-x partials of G1
__device__ float g_A[(size_t)BB * CC * JA];              // [2f_c, -2f_s, f_0, conv_w, pad]
__device__ float g_wct[(size_t)LL * KK * CC * CC];       // wc/size transposed to [l][k][i][o]
__device__ float g_wst[(size_t)LL * KK * CC * CC];

__device__ __forceinline__ float gelu_f(float v) {
    return 0.5f * v * (1.0f + erff(v * 0.70710678118654752f));
}

// ---------------- weight transpose: wc/ws (l,i,o,k) -> (l,k,i,o), /size ----
__global__ void k_wtrans(const float* __restrict__ wc, const float* __restrict__ ws) {
    __shared__ float sm[32][33];
    const int tile = blockIdx.x;              // 16 tiles: (o-tile, k-tile)
    const int o0 = (tile >> 2) * 32, k0 = (tile & 3) * 32;
    const int i = blockIdx.y, l = blockIdx.z;
    const float scale = 1.0f / 8192.0f;
    for (int w = 0; w < 2; w++) {
        const float* src = w ? ws : wc;
        float* dst = w ? g_wst : g_wct;
        #pragma unroll
        for (int s = 0; s < 4; s++) {
            int oo = threadIdx.y + 8 * s, kk = threadIdx.x;
            sm[oo][kk] = src[(((size_t)l * CC + i) * CC + (o0 + oo)) * KK + (k0 + kk)] * scale;
        }
        __syncthreads();
        #pragma unroll
        for (int s = 0; s < 4; s++) {
            int kk = threadIdx.y + 8 * s, oo = threadIdx.x;
            dst[(((size_t)l * KK + (k0 + kk)) * CC + i) * CC + (o0 + oo)] = sm[oo][kk];
        }
        __syncthreads();
    }
}

// ---------------- precompute bases, wsz, h0 = fc0(x) ------------------------
__global__ __launch_bounds__(256) void k_pre(const float* __restrict__ xin,
                                             const float* __restrict__ modes,
                                             const float* __restrict__ fc0_w,
                                             const float* __restrict__ fc0_b) {
    __shared__ float sm_modes[256];
    __shared__ float sm_w[384];
    __shared__ float sm_b[128];
    const int t = threadIdx.x;
    sm_modes[t] = modes[t];
    sm_w[t] = fc0_w[t];
    if (t < 128) { sm_w[256 + t] = fc0_w[256 + t]; sm_b[t] = fc0_b[t]; }
    __syncthreads();

    const int gid = blockIdx.x * 256 + t;     // over B*N
    const int b = gid / NN, xx = gid - b * NN;
    const float* xr = xin + (size_t)gid * 7;
    const float i0 = xr[0], i1 = xr[1], i2 = xr[2];
    const float d0 = xr[3], d1 = xr[4], wgt = xr[5], msk = xr[6];

    g_wsz[gid] = wgt * (float)NN;
    float* bb = g_bases + (size_t)b * J1 * NN + xx;
    bb[(size_t)256 * NN] = msk;
    #pragma unroll 4
    for (int k = 0; k < KK; k++) {
        float tt = fmaf(d0, sm_modes[2 * k], d1 * sm_modes[2 * k + 1]);
        float s, c;
        sincosf(tt, &s, &c);
        bb[(size_t)k * NN] = c * msk;
        bb[(size_t)(128 + k) * NN] = s * msk;
    }
    float* hh = g_h[0] + (size_t)b * CC * NN + xx;
    #pragma unroll 4
    for (int c = 0; c < CC; c++) {
        float v = sm_b[c];
        v = fmaf(i0, sm_w[c], v);
        v = fmaf(i1, sm_w[128 + c], v);
        v = fmaf(i2, sm_w[256 + c], v);
        hh[(size_t)c * NN] = v;
    }
}

// ---------------- G1: partials[s][b][i][j] = sum_x h*wsz * bases[j] --------
// grid (jtile=5, split=8, b=16); block (16,16); 128(i) x 64(j) tile, 8x4 micro
__global__ __launch_bounds__(256) void k_gemm1(int cur) {
    __shared__ float As[32][128];   // [x][i]
    __shared__ float Bs[32][64];    // [x][j] (scaled by wsz)
    __shared__ float wzs[32];
    const int jt = blockIdx.x, sp = blockIdx.y, b = blockIdx.z;
    const int tx = threadIdx.x, ty = threadIdx.y;
    const int tid = ty * 16 + tx;
    const float* hsrc = g_h[cur] + (size_t)b * CC * NN;
    const float* bsrc = g_bases + (size_t)b * J1 * NN;
    const int j0 = jt * 64;
    float acc[8][4];
    #pragma unroll
    for (int i = 0; i < 8; i++)
        #pragma unroll
        for (int j = 0; j < 4; j++) acc[i][j] = 0.f;

    const int ai = tid >> 1;
    const int axs = (tid & 1) * 16;
    const int bjj = tid >> 2;
    const int bxs = (tid & 3) * 8;
    const int jg = j0 + bjj;

    const int xbeg = sp * (NN / NSPLIT), xend = xbeg + (NN / NSPLIT);
    for (int x0 = xbeg; x0 < xend; x0 += 32) {
        if (tid < 32) wzs[tid] = g_wsz[b * NN + x0 + tid];
        __syncthreads();
        {   // A tile: h rows
            const float4* hp = (const float4*)(hsrc + (size_t)ai * NN + x0 + axs);
            #pragma unroll
            for (int u = 0; u < 4; u++) {
                float4 v = hp[u];
                As[axs + u * 4 + 0][ai] = v.x;
                As[axs + u * 4 + 1][ai] = v.y;
                As[axs + u * 4 + 2][ai] = v.z;
                As[axs + u * 4 + 3][ai] = v.w;
            }
        }
        {   // B tile: bases rows * wsz
            float bv[8];
            if (jg < J1) {
                const float* bp = bsrc + (size_t)jg * NN + x0 + bxs;
                #pragma unroll
                for (int u = 0; u < 8; u++) bv[u] = bp[u] * wzs[bxs + u];
            } else {
                #pragma unroll
                for (int u = 0; u < 8; u++) bv[u] = 0.f;
            }
            #pragma unroll
            for (int u = 0; u < 8; u++) Bs[bxs + u][bjj] = bv[u];
        }
        __syncthreads();
        #pragma unroll
        for (int x = 0; x < 32; x++) {
            float a[8], bq[4];
            *(float4*)&a[0] = *(const float4*)&As[x][ty * 8];
            *(float4*)&a[4] = *(const float4*)&As[x][ty * 8 + 4];
            *(float4*)&bq[0] = *(const float4*)&Bs[x][tx * 4];
            #pragma unroll
            for (int i = 0; i < 8; i++)
                #pragma unroll
                for (int j = 0; j < 4; j++) acc[i][j] = fmaf(a[i], bq[j], acc[i][j]);
        }
        // next iter's wzs write only touches wzs (not read in inner loop);
        // the sync after it protects As/Bs reuse.
    }
    float* pp = g_part + (((size_t)sp * BB + b) * CC) * J1;
    #pragma unroll
    for (int i = 0; i < 8; i++) {
        const int row = ty * 8 + i;
        #pragma unroll
        for (int j = 0; j < 4; j++) {
            const int jc = j0 + tx * 4 + j;
            if (jc < J1) pp[(size_t)row * J1 + jc] = acc[i][j];
        }
    }
}

// ---------------- per-k complex mix: build g_A ------------------------------
// grid (K, B); block 128 (= o)
__global__ __launch_bounds__(128) void k_f(const float* __restrict__ w0,
                                           const float* __restrict__ conv_w, int l) {
    const int k = blockIdx.x, b = blockIdx.y;
    const int o = threadIdx.x;
    __shared__ float xc[128], xs[128], x0v[128];
    {
        float sc = 0.f, ss = 0.f, s0 = 0.f;
        #pragma unroll
        for (int s = 0; s < NSPLIT; s++) {
            const float* pp = g_part + (((size_t)s * BB + b) * CC + o) * J1;
            sc += pp[k]; ss += pp[128 + k]; s0 += pp[256];
        }
        xc[o] = sc;
        xs[o] = -ss;      // x_s = -einsum(h, wbases_s)
        x0v[o] = s0;
    }
    __syncthreads();
    const float* wct = g_wct + (((size_t)l * KK + k) * CC) * CC + o;
    const float* wst = g_wst + (((size_t)l * KK + k) * CC) * CC + o;
    float fc = 0.f, fs = 0.f;
    #pragma unroll 8
    for (int i = 0; i < 128; i++) {
        const float wcv = wct[(size_t)i * CC], wsv = wst[(size_t)i * CC];
        const float cv = xc[i], sv = xs[i];
        fc = fmaf(cv, wcv, fc); fc = fmaf(-sv, wsv, fc);
        fs = fmaf(sv, wcv, fs); fs = fmaf(cv, wsv, fs);
    }
    float* Ar = g_A + ((size_t)b * CC + o) * JA;
    Ar[k] = 2.f * fc;
    Ar[128 + k] = -2.f * fs;
    if (k == 0) {
        float f0 = 0.f;
        const float* w0p = w0 + (size_t)l * CC * CC;
        for (int i = 0; i < 128; i++) f0 = fmaf(x0v[i], w0p[(size_t)i * CC + o], f0);
        Ar[256] = f0 * (1.0f / 8192.0f);
        const float* cw = conv_w + ((size_t)l * CC + o) * CC;
        for (int i = 0; i < 128; i++) Ar[257 + i] = cw[i];
        #pragma unroll
        for (int j = 385; j < JA; j++) Ar[j] = 0.f;
    }
}

// ---------------- G2: h' = A @ [bases_c; bases_s; mask; h] + conv_b, gelu ---
// grid (N/128, B); block (16,16); 128(o) x 128(x), 8x8 micro
__global__ __launch_bounds__(256) void k_gemm2(int cur, int nxt,
                                               const float* __restrict__ conv_b, int l) {
    __shared__ float As[8][128];  // [j][o]
    __shared__ float Bs[8][128];  // [j][x]
    const int xt = blockIdx.x, b = blockIdx.y;
    const int tx = threadIdx.x, ty = threadIdx.y;
    const int tid = ty * 16 + tx;
    const int x0 = xt * 128;
    const float* Ab = g_A + (size_t)b * CC * JA;
    const float* bases = g_bases + (size_t)b * J1 * NN;
    const float* hcur = g_h[cur] + (size_t)b * CC * NN;
    float acc[8][8];
    #pragma unroll
    for (int i = 0; i < 8; i++)
        #pragma unroll
        for (int j = 0; j < 8; j++) acc[i][j] = 0.f;

    const int ao = tid >> 1;
    const int ajj = (tid & 1) * 4;
    const int bjj = tid >> 5;
    const int bxx = (tid & 31) * 4;

    for (int j0 = 0; j0 < JA; j0 += 8) {
        float4 av = *(const float4*)(Ab + (size_t)ao * JA + j0 + ajj);
        As[ajj + 0][ao] = av.x; As[ajj + 1][ao] = av.y;
        As[ajj + 2][ao] = av.z; As[ajj + 3][ao] = av.w;
        const int jgl = j0 + bjj;
        float4 bv;
        if (jgl < J1)       bv = *(const float4*)(bases + (size_t)jgl * NN + x0 + bxx);
        else if (jgl < 385) bv = *(const float4*)(hcur + (size_t)(jgl - J1) * NN + x0 + bxx);
        else                bv = make_float4(0.f, 0.f, 0.f, 0.f);
        *(float4*)&Bs[bjj][bxx] = bv;
        __syncthreads();
        #pragma unroll
        for (int jj = 0; jj < 8; jj++) {
            float a[8], bw[8];
            *(float4*)&a[0]  = *(const float4*)&As[jj][ty * 8];
            *(float4*)&a[4]  = *(const float4*)&As[jj][ty * 8 + 4];
            *(float4*)&bw[0] = *(const float4*)&Bs[jj][tx * 8];
            *(float4*)&bw[4] = *(const float4*)&Bs[jj][tx * 8 + 4];
            #pragma unroll
            for (int i = 0; i < 8; i++)
                #pragma unroll
                for (int j = 0; j < 8; j++) acc[i][j] = fmaf(a[i], bw[j], acc[i][j]);
        }
        __syncthreads();
    }
    float* hout = g_h[nxt] + (size_t)b * CC * NN;
    #pragma unroll
    for (int i = 0; i < 8; i++) {
        const int o = ty * 8 + i;
        const float cb = conv_b[l * CC + o];
        float v[8];
        #pragma unroll
        for (int j = 0; j < 8; j++) {
            float t = acc[i][j] + cb;
            v[j] = (l < LL - 1) ? gelu_f(t) : t;
        }
        float* op = hout + (size_t)o * NN + x0 + tx * 8;
        *(float4*)op       = make_float4(v[0], v[1], v[2], v[3]);
        *(float4*)(op + 4) = make_float4(v[4], v[5], v[6], v[7]);
    }
}

// ---------------- final MLP: y = fc2(gelu(fc1(h^T))) ------------------------
// grid (N/128, B); block (16,16); tile 128(f) x 128(x)
__global__ __launch_bounds__(256) void k_final(const float* __restrict__ fc1_w,
                                               const float* __restrict__ fc1_b,
                                               const float* __restrict__ fc2_w,
                                               const float* __restrict__ fc2_b,
                                               float* __restrict__ out) {
    __shared__ float Hs[8][128];   // [c][x]
    __shared__ float Ws[8][128];   // [c][f]
    __shared__ float red[16][128];
    const int xt = blockIdx.x, b = blockIdx.y;
    const int tx = threadIdx.x, ty = threadIdx.y;
    const int tid = ty * 16 + tx;
    const int x0 = xt * 128;
    const float* h = g_h[0] + (size_t)b * CC * NN;   // after L=4 layers, h is in buffer 0
    float acc[8][8];
    #pragma unroll
    for (int i = 0; i < 8; i++)
        #pragma unroll
        for (int j = 0; j < 8; j++) acc[i][j] = 0.f;

    const int lcc = tid >> 5;
    const int lxx = (tid & 31) * 4;
    for (int c0 = 0; c0 < CC; c0 += 8) {
        *(float4*)&Hs[lcc][lxx] = *(const float4*)(h + (size_t)(c0 + lcc) * NN + x0 + lxx);
        *(float4*)&Ws[lcc][lxx] = *(const float4*)(fc1_w + (c0 + lcc) * 128 + lxx);
        __syncthreads();
        #pragma unroll
        for (int cc = 0; cc < 8; cc++) {
            float a[8], bw[8];
            *(float4*)&a[0]  = *(const float4*)&Ws[cc][ty * 8];
            *(float4*)&a[4]  = *(const float4*)&Ws[cc][ty * 8 + 4];
            *(float4*)&bw[0] = *(const float4*)&Hs[cc][tx * 8];
            *(float4*)&bw[4] = *(const float4*)&Hs[cc][tx * 8 + 4];
            #pragma unroll
            for (int i = 0; i < 8; i++)
                #pragma unroll
                for (int j = 0; j < 8; j++) acc[i][j] = fmaf(a[i], bw[j], acc[i][j]);
        }
        __syncthreads();
    }
    float yp[8];
    #pragma unroll
    for (int j = 0; j < 8; j++) yp[j] = 0.f;
    #pragma unroll
    for (int i = 0; i < 8; i++) {
        const int f = ty * 8 + i;
        const float b1 = fc1_b[f], w2 = fc2_w[f];
        #pragma unroll
        for (int j = 0; j < 8; j++) yp[j] = fmaf(w2, gelu_f(acc[i][j] + b1), yp[j]);
    }
    #pragma unroll
    for (int j = 0; j < 8; j++) red[ty][tx * 8 + j] = yp[j];
    __syncthreads();
    if (ty == 0) {
        #pragma unroll
        for (int j = 0; j < 8; j++) {
            float s = fc2_b[0];
            #pragma unroll
            for (int r = 0; r < 16; r++) s += red[r][tx * 8 + j];
            out[(size_t)b * NN + x0 + tx * 8 + j] = s;
        }
    }
}

// ---------------- launch -----------------------------------------------------
extern "C" void kernel_launch(void* const* d_in, const int* in_sizes, int n_in,
                              void* d_out, int out_size) {
    const float* x      = (const float*)d_in[0];
    const float* modes  = (const float*)d_in[1];
    const float* fc0_w  = (const float*)d_in[2];
    const float* fc0_b  = (const float*)d_in[3];
    const float* wc     = (const float*)d_in[4];
    const float* ws     = (const float*)d_in[5];
    const float* w0     = (const float*)d_in[6];
    const float* conv_w = (const float*)d_in[7];
    const float* conv_b = (const float*)d_in[8];
    const float* fc1_w  = (const float*)d_in[9];
    const float* fc1_b  = (const float*)d_in[10];
    const float* fc2_w  = (const float*)d_in[11];
    const float* fc2_b  = (const float*)d_in[12];
    float* out = (float*)d_out;

    k_wtrans<<<dim3(16, 128, 4), dim3(32, 8)>>>(wc, ws);
    k_pre<<<(BB * NN) / 256, 256>>>(x, modes, fc0_w, fc0_b);
    for (int l = 0; l < LL; l++) {
        const int cur = l & 1, nxt = cur ^ 1;
        k_gemm1<<<dim3(5, NSPLIT, BB), dim3(16, 16)>>>(cur);
        k_f<<<dim3(KK, BB), 128>>>(w0, conv_w, l);
        k_gemm2<<<dim3(NN / 128, BB), dim3(16, 16)>>>(cur, nxt, conv_b, l);
    }
    k_final<<<dim3(NN / 128, BB), dim3(16, 16)>>>(fc1_w, fc1_b, fc2_w, fc2_b, out);
}